// round 11
// baseline (speedup 1.0000x reference)
#include <cuda_runtime.h>
#include <cuda_bf16.h>
#include <math.h>
#include <stdint.h>

#define Bz   8
#define Sq   1024
#define Dm   1024
#define Hn   16
#define HDim 64
#define Ff   4096
#define NL   6
#define NTOK (Bz*Sq)   /* 8192 tokens */

// fp32 scratch: X, T2
__device__ float g_f32[(size_t)NTOK*Dm*2];
// bf16 hi/lo activation buffers
__device__ __nv_bfloat16 g_xh[(size_t)NTOK*Dm],    g_xl[(size_t)NTOK*Dm];
__device__ __nv_bfloat16 g_qkvh[(size_t)NTOK*3*Dm], g_qkvl[(size_t)NTOK*3*Dm];
__device__ __nv_bfloat16 g_oh[(size_t)NTOK*Dm],    g_ol[(size_t)NTOK*Dm];
__device__ __nv_bfloat16 g_hh[(size_t)NTOK*Ff],    g_hl[(size_t)NTOK*Ff];
// bf16 hi/lo transposed weights: per layer 12M elems (Wqkv 3M, Wo 1M, W1t 4M, W2t 4M)
__device__ __nv_bfloat16 g_wt_hi[(size_t)NL*12*1024*1024];
__device__ __nv_bfloat16 g_wt_lo[(size_t)NL*12*1024*1024];
// packed QKV bias
__device__ float g_bqkv[(size_t)NL*3*Dm];

// ---------------------------------------------------------------------------
// helpers
// ---------------------------------------------------------------------------
__device__ __forceinline__ uint32_t smem_u32(const void* p) {
    uint32_t a;
    asm("{ .reg .u64 t; cvta.to.shared.u64 t, %1; cvt.u32.u64 %0, t; }" : "=r"(a) : "l"(p));
    return a;
}
__device__ __forceinline__ void ldsm4(uint32_t* r, uint32_t addr) {
    asm volatile("ldmatrix.sync.aligned.m8n8.x4.shared.b16 {%0,%1,%2,%3}, [%4];"
        : "=r"(r[0]), "=r"(r[1]), "=r"(r[2]), "=r"(r[3]) : "r"(addr));
}
__device__ __forceinline__ void ldsm4t(uint32_t* r, uint32_t addr) {
    asm volatile("ldmatrix.sync.aligned.m8n8.x4.trans.shared.b16 {%0,%1,%2,%3}, [%4];"
        : "=r"(r[0]), "=r"(r[1]), "=r"(r[2]), "=r"(r[3]) : "r"(addr));
}
__device__ __forceinline__ void mma16816(float* c, const uint32_t* a, const uint32_t* b) {
    asm volatile(
        "mma.sync.aligned.m16n8k16.row.col.f32.bf16.bf16.f32 "
        "{%0,%1,%2,%3}, {%4,%5,%6,%7}, {%8,%9}, {%0,%1,%2,%3};"
        : "+f"(c[0]), "+f"(c[1]), "+f"(c[2]), "+f"(c[3])
        : "r"(a[0]), "r"(a[1]), "r"(a[2]), "r"(a[3]), "r"(b[0]), "r"(b[1]));
}
// two fp32 -> packed bf16x2 hi + bf16x2 lo (residual)
__device__ __forceinline__ void split2(float x, float y, uint32_t& hi, uint32_t& lo) {
    __nv_bfloat162 h = __floats2bfloat162_rn(x, y);
    __nv_bfloat162 l = __floats2bfloat162_rn(x - __low2float(h), y - __high2float(h));
    hi = *reinterpret_cast<uint32_t*>(&h);
    lo = *reinterpret_cast<uint32_t*>(&l);
}

// ---------------------------------------------------------------------------
// Embedding * sqrt(D) + sinusoidal PE (+ hi/lo split)
// ---------------------------------------------------------------------------
__global__ void embed_kernel(const int* __restrict__ src, const float* __restrict__ emb,
                             float* __restrict__ X, __nv_bfloat16* __restrict__ Xh,
                             __nv_bfloat16* __restrict__ Xl)
{
    int row = blockIdx.x;
    int s   = row % Sq;
    int tok = src[row];
    const float* er = emb + (size_t)tok * Dm;
    size_t base = (size_t)row * Dm;
    #pragma unroll
    for (int e = 0; e < 4; e++) {
        int d  = threadIdx.x + e * 256;
        int j2 = (d >> 1) * 2;
        float div = powf(10000.0f, (float)j2 / (float)Dm);
        float ang = (float)s / div;
        float pe  = (d & 1) ? cosf(ang) : sinf(ang);
        float v = er[d] * 32.0f + pe;
        X[base + d] = v;
        __nv_bfloat16 h = __float2bfloat16(v);
        Xh[base + d] = h;
        Xl[base + d] = __float2bfloat16(v - __bfloat162float(h));
    }
}

// ---------------------------------------------------------------------------
// Weight transpose + hi/lo split, batched over layers via blockIdx.z
// ---------------------------------------------------------------------------
__global__ __launch_bounds__(256)
void wt_convz_kernel(const float* __restrict__ W, __nv_bfloat16* __restrict__ Thi,
                     __nv_bfloat16* __restrict__ Tlo, int K, int N,
                     size_t src_stride, size_t dst_stride)
{
    int l = blockIdx.z;
    W   += (size_t)l * src_stride;
    Thi += (size_t)l * dst_stride;
    Tlo += (size_t)l * dst_stride;
    __shared__ float t[32][33];
    int n0 = blockIdx.x * 32, k0 = blockIdx.y * 32;
    int tx = threadIdx.x & 31, ty = threadIdx.x >> 5;
    #pragma unroll
    for (int j = 0; j < 4; j++)
        t[ty + j*8][tx] = W[(size_t)(k0 + ty + j*8) * N + n0 + tx];
    __syncthreads();
    #pragma unroll
    for (int j = 0; j < 4; j++) {
        float v = t[tx][ty + j*8];
        __nv_bfloat16 h = __float2bfloat16(v);
        __nv_bfloat16 lo = __float2bfloat16(v - __bfloat162float(h));
        size_t idx = (size_t)(n0 + ty + j*8) * K + k0 + tx;
        Thi[idx] = h; Tlo[idx] = lo;
    }
}

__global__ void pack_bias_kernel(const float* __restrict__ bq, const float* __restrict__ bk,
                                 const float* __restrict__ bv, float* __restrict__ dst)
{
    int idx = blockIdx.x * 256 + threadIdx.x;
    int l = idx / (3*Dm), j = idx % (3*Dm);
    float v = (j < Dm) ? bq[l*Dm + j] : (j < 2*Dm) ? bk[l*Dm + j - Dm] : bv[l*Dm + j - 2*Dm];
    dst[idx] = v;
}

// ---------------------------------------------------------------------------
// HMMA bf16-split GEMM: C = A @ W + bias (+ReLU)
// 128x256 CTA tile, 8 warps (2M x 4N), warp tile 64x64, BK=64 stages with
// BK=32 commit granularity: 2 stages x 2 halves = 4-unit cp.async ring.
// ---------------------------------------------------------------------------
#define G_AH 0
#define G_AL 16384
#define G_BH 32768
#define G_BL 65536
#define STAGEB 98304
#define GEMM_SMEM (2*STAGEB)      /* 196608 */

__device__ __forceinline__ void load_unit(
    uint32_t sb, const __nv_bfloat16* Ahi, const __nv_bfloat16* Alo,
    const __nv_bfloat16* Bhi, const __nv_bfloat16* Blo,
    int bm, int bn, int K, int u, int tid)
{
    uint32_t stg = sb + (((u >> 1) & 1) ? STAGEB : 0);
    int h = u & 1;
    size_t kg = (size_t)u * 32;
    // A tiles: 128 rows x 4 chunks (hi + lo)
    #pragma unroll
    for (int i = 0; i < 2; i++) {
        int idx = tid + i * 256;
        int row = idx >> 2, cl = idx & 3;
        int chunk = 4 * h + cl;
        uint32_t off = row * 128 + ((chunk ^ (row & 7)) << 4);
        const void* gh = Ahi + (size_t)(bm + row) * K + kg + cl * 8;
        const void* gl = Alo + (size_t)(bm + row) * K + kg + cl * 8;
        asm volatile("cp.async.cg.shared.global [%0], [%1], 16;" :: "r"(stg + G_AH + off), "l"(gh));
        asm volatile("cp.async.cg.shared.global [%0], [%1], 16;" :: "r"(stg + G_AL + off), "l"(gl));
    }
    // B tiles: 256 rows x 4 chunks (hi + lo)
    #pragma unroll
    for (int i = 0; i < 4; i++) {
        int idx = tid + i * 256;
        int row = idx >> 2, cl = idx & 3;
        int chunk = 4 * h + cl;
        uint32_t off = row * 128 + ((chunk ^ (row & 7)) << 4);
        const void* gh = Bhi + (size_t)(bn + row) * K + kg + cl * 8;
        const void* gl = Blo + (size_t)(bn + row) * K + kg + cl * 8;
        asm volatile("cp.async.cg.shared.global [%0], [%1], 16;" :: "r"(stg + G_BH + off), "l"(gh));
        asm volatile("cp.async.cg.shared.global [%0], [%1], 16;" :: "r"(stg + G_BL + off), "l"(gl));
    }
    asm volatile("cp.async.commit_group;" ::: "memory");
}

__global__ __launch_bounds__(256, 1)
void gemm_tc_kernel(const __nv_bfloat16* __restrict__ Ahi, const __nv_bfloat16* __restrict__ Alo,
                    const __nv_bfloat16* __restrict__ Bhi, const __nv_bfloat16* __restrict__ Blo,
                    const float* __restrict__ bias, float* __restrict__ Cf,
                    __nv_bfloat16* __restrict__ Chi, __nv_bfloat16* __restrict__ Clo,
                    int M, int N, int K, int relu)
{
    extern __shared__ __align__(1024) char smem[];
    uint32_t sb  = smem_u32(smem);
    int tid = threadIdx.x, wid = tid >> 5, lane = tid & 31;
    int bn = blockIdx.x * 256, bm = blockIdx.y * 128;
    int KU = K >> 5;    // K32 units

    int r0 = (wid & 1) * 64;     // warp M base
    int n0 = (wid >> 1) * 64;    // warp N base

    float acc[4][8][4];
    #pragma unroll
    for (int a = 0; a < 4; a++)
        #pragma unroll
        for (int b = 0; b < 8; b++)
            #pragma unroll
            for (int c = 0; c < 4; c++) acc[a][b][c] = 0.f;

    load_unit(sb, Ahi, Alo, Bhi, Blo, bm, bn, K, 0, tid);
    load_unit(sb, Ahi, Alo, Bhi, Blo, bm, bn, K, 1, tid);
    load_unit(sb, Ahi, Alo, Bhi, Blo, bm, bn, K, 2, tid);

    int a_ri = ((lane >> 3) & 1) * 8 + (lane & 7);
    int a_ci = (lane >> 4);
    int b_ri = ((lane >> 4) << 3) + (lane & 7);
    int b_ci = ((lane >> 3) & 1);

    for (int u = 0; u < KU; u++) {
        int rem = KU - 1 - u;
        if (rem >= 2)      asm volatile("cp.async.wait_group 2;" ::: "memory");
        else if (rem == 1) asm volatile("cp.async.wait_group 1;" ::: "memory");
        else               asm volatile("cp.async.wait_group 0;" ::: "memory");
        __syncthreads();

        if (u + 3 < KU)
            load_unit(sb, Ahi, Alo, Bhi, Blo, bm, bn, K, u + 3, tid);

        uint32_t stg = sb + (((u >> 1) & 1) ? STAGEB : 0);
        int h = u & 1;

        #pragma unroll
        for (int ksl = 0; ksl < 2; ksl++) {
            int cbase = 4 * h + 2 * ksl;
            uint32_t aH[4][4], aL[4][4];
            int achk = cbase + a_ci;
            #pragma unroll
            for (int mf = 0; mf < 4; mf++) {
                int row = r0 + mf * 16 + a_ri;
                uint32_t off = row * 128 + ((achk ^ (row & 7)) << 4);
                ldsm4(aH[mf], stg + G_AH + off);
                ldsm4(aL[mf], stg + G_AL + off);
            }
            int bchk = cbase + b_ci;
            #pragma unroll
            for (int g = 0; g < 4; g++) {
                int row = n0 + g * 16 + b_ri;
                uint32_t off = row * 128 + ((bchk ^ (row & 7)) << 4);
                uint32_t tH[4], tL[4];
                ldsm4(tH, stg + G_BH + off);
                ldsm4(tL, stg + G_BL + off);
                #pragma unroll
                for (int mf = 0; mf < 4; mf++) {
                    mma16816(acc[mf][2*g],   aH[mf], tH);
                    mma16816(acc[mf][2*g],   aL[mf], tH);
                    mma16816(acc[mf][2*g],   aH[mf], tL);
                    mma16816(acc[mf][2*g+1], aH[mf], tH + 2);
                    mma16816(acc[mf][2*g+1], aL[mf], tH + 2);
                    mma16816(acc[mf][2*g+1], aH[mf], tL + 2);
                }
            }
        }
    }

    int lrow = lane >> 2, lcol = (lane & 3) * 2;
    #pragma unroll
    for (int mf = 0; mf < 4; mf++) {
        int row = bm + r0 + mf * 16 + lrow;
        #pragma unroll
        for (int nf = 0; nf < 8; nf++) {
            int col = bn + n0 + nf * 8 + lcol;
            float b0 = bias[col], b1 = bias[col + 1];
            float2 v0, v1;
            v0.x = acc[mf][nf][0] + b0; v0.y = acc[mf][nf][1] + b1;
            v1.x = acc[mf][nf][2] + b0; v1.y = acc[mf][nf][3] + b1;
            if (relu) {
                v0.x = fmaxf(v0.x, 0.f); v0.y = fmaxf(v0.y, 0.f);
                v1.x = fmaxf(v1.x, 0.f); v1.y = fmaxf(v1.y, 0.f);
            }
            if (Cf) {
                *(float2*)(Cf + (size_t)row * N + col)       = v0;
                *(float2*)(Cf + (size_t)(row + 8) * N + col) = v1;
            }
            if (Chi) {
                uint32_t h0, l0u, h1, l1u;
                split2(v0.x, v0.y, h0, l0u);
                split2(v1.x, v1.y, h1, l1u);
                *(uint32_t*)(Chi + (size_t)row * N + col)       = h0;
                *(uint32_t*)(Clo + (size_t)row * N + col)       = l0u;
                *(uint32_t*)(Chi + (size_t)(row + 8) * N + col) = h1;
                *(uint32_t*)(Clo + (size_t)(row + 8) * N + col) = l1u;
            }
        }
    }
}

// ---------------------------------------------------------------------------
// Tensor-core flash attention (bf16 hi/lo split, fp32 accum)
// ---------------------------------------------------------------------------
#define A_QH 0
#define A_QL 16384
#define A_ST 32768
#define A_MSK 163840
#define ATTN_SMEM (163840 + 4096)

__device__ __forceinline__ void attn_load_tile(uint32_t dst, const __nv_bfloat16* src,
                                               size_t row0, int colbase, int tid)
{
    #pragma unroll
    for (int i = 0; i < 4; i++) {
        int c = tid + i * 256;
        int row = c >> 3, cb = c & 7;
        uint32_t d = dst + row * 128 + ((cb ^ (row & 7)) << 4);
        const void* gp = src + (row0 + row) * (size_t)(3 * Dm) + colbase + cb * 8;
        asm volatile("cp.async.cg.shared.global [%0], [%1], 16;" :: "r"(d), "l"(gp));
    }
}

__global__ __launch_bounds__(256, 1)
void attn_tc_kernel(const __nv_bfloat16* __restrict__ QKVh, const __nv_bfloat16* __restrict__ QKVl,
                    const int* __restrict__ mask, __nv_bfloat16* __restrict__ Oh,
                    __nv_bfloat16* __restrict__ Ol)
{
    extern __shared__ __align__(1024) char smem[];
    uint32_t sb = smem_u32(smem);
    int tid = threadIdx.x, wid = tid >> 5, lane = tid & 31;
    int q0 = blockIdx.x * 128, h = blockIdx.y, b = blockIdx.z;

    int* msm = (int*)(smem + A_MSK);
    #pragma unroll
    for (int i = 0; i < 4; i++) msm[tid + i * 256] = mask[b * Sq + tid + i * 256];

    size_t rowQ = (size_t)b * Sq + q0;
    attn_load_tile(sb + A_QH, QKVh, rowQ, h * HDim, tid);
    attn_load_tile(sb + A_QL, QKVl, rowQ, h * HDim, tid);
    asm volatile("cp.async.commit_group;" ::: "memory");
    size_t rowK = (size_t)b * Sq;
    attn_load_tile(sb + A_ST,         QKVh, rowK, Dm + h * HDim, tid);
    attn_load_tile(sb + A_ST + 16384, QKVl, rowK, Dm + h * HDim, tid);
    attn_load_tile(sb + A_ST + 32768, QKVh, rowK, 2 * Dm + h * HDim, tid);
    attn_load_tile(sb + A_ST + 49152, QKVl, rowK, 2 * Dm + h * HDim, tid);
    asm volatile("cp.async.commit_group;" ::: "memory");

    float m0 = -1e30f, m1 = -1e30f, l0 = 0.f, l1 = 0.f;
    float acc[8][4];
    #pragma unroll
    for (int o = 0; o < 8; o++)
        #pragma unroll
        for (int e = 0; e < 4; e++) acc[o][e] = 0.f;

    int a_ri = ((lane >> 3) & 1) * 8 + (lane & 7);
    int a_ci = (lane >> 4);
    int b_ri = ((lane >> 4) << 3) + (lane & 7);
    int b_ci = ((lane >> 3) & 1);

    for (int c = 0; c < 8; c++) {
        if (c < 7) {
            uint32_t stg = sb + A_ST + ((c + 1) & 1) * 65536;
            size_t rk = (size_t)b * Sq + (c + 1) * 128;
            attn_load_tile(stg,         QKVh, rk, Dm + h * HDim, tid);
            attn_load_tile(stg + 16384, QKVl, rk, Dm + h * HDim, tid);
            attn_load_tile(stg + 32768, QKVh, rk, 2 * Dm + h * HDim, tid);
            attn_load_tile(stg + 49152, QKVl, rk, 2 * Dm + h * HDim, tid);
            asm volatile("cp.async.commit_group;" ::: "memory");
            asm volatile("cp.async.wait_group 1;" ::: "memory");
        } else {
            asm volatile("cp.async.wait_group 0;" ::: "memory");
        }
        __syncthreads();

        uint32_t stg = sb + A_ST + (c & 1) * 65536;
        uint32_t KH = stg, KL = stg + 16384, VH = stg + 32768, VL = stg + 49152;

        float s[16][4];
        #pragma unroll
        for (int nf = 0; nf < 16; nf++)
            #pragma unroll
            for (int e = 0; e < 4; e++) s[nf][e] = 0.f;

        #pragma unroll
        for (int ks = 0; ks < 4; ks++) {
            uint32_t aH[4], aL[4];
            int qrow = wid * 16 + a_ri;
            uint32_t aoff = qrow * 128 + (((ks * 2 + a_ci) ^ (qrow & 7)) << 4);
            ldsm4(aH, sb + A_QH + aoff);
            ldsm4(aL, sb + A_QL + aoff);
            #pragma unroll
            for (int g = 0; g < 8; g++) {
                int krow = g * 16 + b_ri;
                uint32_t boff = krow * 128 + (((ks * 2 + b_ci) ^ (krow & 7)) << 4);
                uint32_t tH[4], tL[4];
                ldsm4(tH, KH + boff);
                ldsm4(tL, KL + boff);
                mma16816(s[2*g],   aH, tH);
                mma16816(s[2*g],   aL, tH);
                mma16816(s[2*g],   aH, tL);
                mma16816(s[2*g+1], aH, tH + 2);
                mma16816(s[2*g+1], aL, tH + 2);
                mma16816(s[2*g+1], aH, tL + 2);
            }
        }

        int k0c = c * 128;
        #pragma unroll
        for (int nf = 0; nf < 16; nf++) {
            int col = k0c + nf * 8 + (lane & 3) * 2;
            float ad0 = (msm[col]     == 0) ? -1e10f : 0.f;
            float ad1 = (msm[col + 1] == 0) ? -1e10f : 0.f;
            s[nf][0] = s[nf][0] * 0.125f + ad0;
            s[nf][1] = s[nf][1] * 0.125f + ad1;
            s[nf][2] = s[nf][2] * 0.125f + ad0;
            s[nf][3] = s[nf][3] * 0.125f + ad1;
        }

        float tm0 = -1e30f, tm1 = -1e30f;
        #pragma unroll
        for (int nf = 0; nf < 16; nf++) {
            tm0 = fmaxf(tm0, fmaxf(s[nf][0], s[nf][1]));
            tm1 = fmaxf(tm1, fmaxf(s[nf][2], s[nf][3]));
        }
        tm0 = fmaxf(tm0, __shfl_xor_sync(0xffffffffu, tm0, 1));
        tm0 = fmaxf(tm0, __shfl_xor_sync(0xffffffffu, tm0, 2));
        tm1 = fmaxf(tm1, __shfl_xor_sync(0xffffffffu, tm1, 1));
        tm1 = fmaxf(tm1, __shfl_xor_sync(0xffffffffu, tm1, 2));
        float nm0 = fmaxf(m0, tm0), nm1 = fmaxf(m1, tm1);
        float cr0 = __expf(m0 - nm0), cr1 = __expf(m1 - nm1);
        float rs0 = 0.f, rs1 = 0.f;
        #pragma unroll
        for (int nf = 0; nf < 16; nf++) {
            s[nf][0] = __expf(s[nf][0] - nm0); rs0 += s[nf][0];
            s[nf][1] = __expf(s[nf][1] - nm0); rs0 += s[nf][1];
            s[nf][2] = __expf(s[nf][2] - nm1); rs1 += s[nf][2];
            s[nf][3] = __expf(s[nf][3] - nm1); rs1 += s[nf][3];
        }
        rs0 += __shfl_xor_sync(0xffffffffu, rs0, 1);
        rs0 += __shfl_xor_sync(0xffffffffu, rs0, 2);
        rs1 += __shfl_xor_sync(0xffffffffu, rs1, 1);
        rs1 += __shfl_xor_sync(0xffffffffu, rs1, 2);
        l0 = l0 * cr0 + rs0;  l1 = l1 * cr1 + rs1;
        m0 = nm0;  m1 = nm1;
        #pragma unroll
        for (int o = 0; o < 8; o++) {
            acc[o][0] *= cr0; acc[o][1] *= cr0;
            acc[o][2] *= cr1; acc[o][3] *= cr1;
        }

        #pragma unroll
        for (int kp = 0; kp < 8; kp++) {
            uint32_t pH[4], pL[4];
            split2(s[2*kp][0],   s[2*kp][1],   pH[0], pL[0]);
            split2(s[2*kp][2],   s[2*kp][3],   pH[1], pL[1]);
            split2(s[2*kp+1][0], s[2*kp+1][1], pH[2], pL[2]);
            split2(s[2*kp+1][2], s[2*kp+1][3], pH[3], pL[3]);
            int vrow = kp * 16 + (lane & 7) + ((lane >> 3) & 1) * 8;
            int vck  = (lane >> 4);
            #pragma unroll
            for (int vg = 0; vg < 4; vg++) {
                uint32_t off = vrow * 128 + (((vg * 2 + vck) ^ (vrow & 7)) << 4);
                uint32_t tH[4], tL[4];
                ldsm4t(tH, VH + off);
                ldsm4t(tL, VL + off);
                mma16816(acc[2*vg],   pH, tH);
                mma16816(acc[2*vg],   pL, tH);
                mma16816(acc[2*vg],   pH, tL);
                mma16816(acc[2*vg+1], pH, tH + 2);
                mma16816(acc[2*vg+1], pL, tH + 2);
                mma16816(acc[2*vg+1], pH, tL + 2);
            }
        }
        __syncthreads();
    }

    float i0 = 1.f / l0, i1 = 1.f / l1;
    size_t base0 = ((size_t)b * Sq + q0 + wid * 16 + (lane >> 2)) * Dm + h * HDim + (lane & 3) * 2;
    size_t base1 = base0 + (size_t)8 * Dm;
    #pragma unroll
    for (int nf = 0; nf < 8; nf++) {
        uint32_t h0, l0u, h1, l1u;
        split2(acc[nf][0] * i0, acc[nf][1] * i0, h0, l0u);
        split2(acc[nf][2] * i1, acc[nf][3] * i1, h1, l1u);
        *(uint32_t*)(Oh + base0 + nf * 8) = h0;
        *(uint32_t*)(Ol + base0 + nf * 8) = l0u;
        *(uint32_t*)(Oh + base1 + nf * 8) = h1;
        *(uint32_t*)(Ol + base1 + nf * 8) = l1u;
    }
}

// ---------------------------------------------------------------------------
// dst = LayerNorm(x + t) * g + b  (+ optional hi/lo split outputs)
// ---------------------------------------------------------------------------
__device__ __forceinline__ float block_reduce_sum(float v, float* red)
{
    #pragma unroll
    for (int o = 16; o > 0; o >>= 1) v += __shfl_xor_sync(0xffffffffu, v, o);
    int w = threadIdx.x >> 5;
    if ((threadIdx.x & 31) == 0) red[w] = v;
    __syncthreads();
    if (threadIdx.x < 32) {
        float r = (threadIdx.x < 8) ? red[threadIdx.x] : 0.f;
        #pragma unroll
        for (int o = 4; o > 0; o >>= 1) r += __shfl_xor_sync(0xffffffffu, r, o);
        if (threadIdx.x == 0) red[0] = r;
    }
    __syncthreads();
    float r = red[0];
    __syncthreads();
    return r;
}

__global__ __launch_bounds__(256)
void add_ln_kernel(const float* __restrict__ x, const float* __restrict__ t,
                   const float* __restrict__ g, const float* __restrict__ bt,
                   float* __restrict__ dst, __nv_bfloat16* __restrict__ dhi,
                   __nv_bfloat16* __restrict__ dlo)
{
    __shared__ float red[8];
    size_t base = (size_t)blockIdx.x * Dm;
    float v[4]; float s = 0.f;
    #pragma unroll
    for (int e = 0; e < 4; e++) {
        int c = threadIdx.x + e * 256;
        v[e] = x[base + c] + t[base + c];
        s += v[e];
    }
    s = block_reduce_sum(s, red);
    float mu = s * (1.0f / Dm);
    float q = 0.f;
    #pragma unroll
    for (int e = 0; e < 4; e++) { float d = v[e] - mu; q += d * d; }
    q = block_reduce_sum(q, red);
    float inv = rsqrtf(q * (1.0f / Dm) + 1e-5f);
    #pragma unroll
    for (int e = 0; e < 4; e++) {
        int c = threadIdx.x + e * 256;
        float o = (v[e] - mu) * inv * g[c] + bt[c];
        dst[base + c] = o;
        if (dhi) {
            __nv_bfloat16 h = __float2bfloat16(o);
            dhi[base + c] = h;
            dlo[base + c] = __float2bfloat16(o - __bfloat162float(h));
        }
    }
}

// ---------------------------------------------------------------------------
extern "C" void kernel_launch(void* const* d_in, const int* in_sizes, int n_in,
                              void* d_out, int out_size)
{
    const int*   src = (const int*)d_in[0];
    const int*   msk = (const int*)d_in[1];
    const float* emb = (const float*)d_in[2];
    const float* Wq  = (const float*)d_in[3];
    const float* bq  = (const float*)d_in[4];
    const float* Wk  = (const float*)d_in[5];
    const float* bk  = (const float*)d_in[6];
    const float* Wv  = (const float*)d_in[7];
    const float* bv  = (const float*)d_in[8];
    const float* Wo  = (const float*)d_in[9];
    const float* bo  = (const float*)d_in[10];
    const float* g1  = (const float*)d_in[11];
    const float* b1n = (const float*)d_in[12];
    const float* W1  = (const float*)d_in[13];
    const float* b1  = (const float*)d_in[14];
    const float* W2  = (const float*)d_in[15];
    const float* b2  = (const float*)d_in[16];
    const float* g2  = (const float*)d_in[17];
    const float* b2n = (const float*)d_in[18];
    float* out = (float*)d_out;

    float* f32 = nullptr;
    cudaGetSymbolAddress((void**)&f32, g_f32);
    float* X  = f32;
    float* T2 = f32 + (size_t)NTOK * Dm;

    __nv_bfloat16 *Xh, *Xl, *Qh, *Ql, *Ohb, *Olb, *Hh, *Hl, *Wh, *Wl;
    float* bqkv;
    cudaGetSymbolAddress((void**)&Xh,  g_xh);
    cudaGetSymbolAddress((void**)&Xl,  g_xl);
    cudaGetSymbolAddress((void**)&Qh,  g_qkvh);
    cudaGetSymbolAddress((void**)&Ql,  g_qkvl);
    cudaGetSymbolAddress((void**)&Ohb, g_oh);
    cudaGetSymbolAddress((void**)&Olb, g_ol);
    cudaGetSymbolAddress((void**)&Hh,  g_hh);
    cudaGetSymbolAddress((void**)&Hl,  g_hl);
    cudaGetSymbolAddress((void**)&Wh,  g_wt_hi);
    cudaGetSymbolAddress((void**)&Wl,  g_wt_lo);
    cudaGetSymbolAddress((void**)&bqkv, g_bqkv);

    cudaFuncSetAttribute((const void*)gemm_tc_kernel,
                         cudaFuncAttributeMaxDynamicSharedMemorySize, GEMM_SMEM);
    cudaFuncSetAttribute((const void*)attn_tc_kernel,
                         cudaFuncAttributeMaxDynamicSharedMemorySize, ATTN_SMEM);

    const size_t M1  = (size_t)1024 * 1024;
    const size_t LWT = 12 * M1;

    wt_convz_kernel<<<dim3(32, 32, NL), 256>>>(Wq, Wh,          Wl,          Dm, Dm, (size_t)Dm*Dm, LWT);
    wt_convz_kernel<<<dim3(32, 32, NL), 256>>>(Wk, Wh + M1,     Wl + M1,     Dm, Dm, (size_t)Dm*Dm, LWT);
    wt_convz_kernel<<<dim3(32, 32, NL), 256>>>(Wv, Wh + 2*M1,   Wl + 2*M1,   Dm, Dm, (size_t)Dm*Dm, LWT);
    wt_convz_kernel<<<dim3(32, 32, NL), 256>>>(Wo, Wh + 3*M1,   Wl + 3*M1,   Dm, Dm, (size_t)Dm*Dm, LWT);
    wt_convz_kernel<<<dim3(Ff/32, Dm/32, NL), 256>>>(W1, Wh + 4*M1, Wl + 4*M1, Dm, Ff, (size_t)Dm*Ff, LWT);
    wt_convz_kernel<<<dim3(Dm/32, Ff/32, NL), 256>>>(W2, Wh + 8*M1, Wl + 8*M1, Ff, Dm, (size_t)Dm*Ff, LWT);
    pack_bias_kernel<<<NL * 3 * Dm / 256, 256>>>(bq, bk, bv, bqkv);

    embed_kernel<<<NTOK, 256>>>(src, emb, X, Xh, Xl);

    dim3 gQKV(3 * Dm / 256, NTOK / 128);  // (12, 64)
    dim3 gD(Dm / 256, NTOK / 128);        // (4, 64)
    dim3 gF(Ff / 256, NTOK / 128);        // (16, 64)
    dim3 gA(Sq / 128, Hn, Bz);            // (8, 16, 8)

    for (int l = 0; l < NL; l++) {
        size_t oD = (size_t)l * Dm, oF = (size_t)l * Ff;
        size_t wb = (size_t)l * LWT;
        bool last = (l == NL - 1);

        gemm_tc_kernel<<<gQKV, 256, GEMM_SMEM>>>(Xh, Xl, Wh + wb, Wl + wb,
            bqkv + (size_t)l * 3 * Dm, nullptr, Qh, Ql, NTOK, 3 * Dm, Dm, 0);
        attn_tc_kernel<<<gA, 256, ATTN_SMEM>>>(Qh, Ql, msk, Ohb, Olb);
        gemm_tc_kernel<<<gD, 256, GEMM_SMEM>>>(Ohb, Olb, Wh + wb + 3*M1, Wl + wb + 3*M1,
            bo + oD, T2, nullptr, nullptr, NTOK, Dm, Dm, 0);
        add_ln_kernel<<<NTOK, 256>>>(X, T2, g1 + oD, b1n + oD, X, Xh, Xl);
        gemm_tc_kernel<<<gF, 256, GEMM_SMEM>>>(Xh, Xl, Wh + wb + 4*M1, Wl + wb + 4*M1,
            b1 + oF, nullptr, Hh, Hl, NTOK, Ff, Dm, 1);
        gemm_tc_kernel<<<gD, 256, GEMM_SMEM>>>(Hh, Hl, Wh + wb + 8*M1, Wl + wb + 8*M1,
            b2 + oD, T2, nullptr, nullptr, NTOK, Dm, Ff, 0);
        add_ln_kernel<<<NTOK, 256>>>(X, T2, g2 + oD, b2n + oD,
            last ? out : X, last ? nullptr : Xh, Xl);
    }
}

// round 12
// speedup vs baseline: 1.0031x; 1.0031x over previous
#include <cuda_runtime.h>
#include <cuda_bf16.h>
#include <math.h>
#include <stdint.h>

#define Bz   8
#define Sq   1024
#define Dm   1024
#define Hn   16
#define HDim 64
#define Ff   4096
#define NL   6
#define NTOK (Bz*Sq)   /* 8192 tokens */

// fp32 scratch: X, T2
__device__ float g_f32[(size_t)NTOK*Dm*2];
// bf16 hi/lo activation buffers
__device__ __nv_bfloat16 g_xh[(size_t)NTOK*Dm],    g_xl[(size_t)NTOK*Dm];
__device__ __nv_bfloat16 g_qkvh[(size_t)NTOK*3*Dm], g_qkvl[(size_t)NTOK*3*Dm];
__device__ __nv_bfloat16 g_oh[(size_t)NTOK*Dm],    g_ol[(size_t)NTOK*Dm];
__device__ __nv_bfloat16 g_hh[(size_t)NTOK*Ff],    g_hl[(size_t)NTOK*Ff];
// bf16 hi/lo transposed weights: per layer 12M elems (Wqkv 3M, Wo 1M, W1t 4M, W2t 4M)
__device__ __nv_bfloat16 g_wt_hi[(size_t)NL*12*1024*1024];
__device__ __nv_bfloat16 g_wt_lo[(size_t)NL*12*1024*1024];
// packed QKV bias
__device__ float g_bqkv[(size_t)NL*3*Dm];

// ---------------------------------------------------------------------------
// helpers
// ---------------------------------------------------------------------------
__device__ __forceinline__ uint32_t smem_u32(const void* p) {
    uint32_t a;
    asm("{ .reg .u64 t; cvta.to.shared.u64 t, %1; cvt.u32.u64 %0, t; }" : "=r"(a) : "l"(p));
    return a;
}
__device__ __forceinline__ void ldsm4(uint32_t* r, uint32_t addr) {
    asm volatile("ldmatrix.sync.aligned.m8n8.x4.shared.b16 {%0,%1,%2,%3}, [%4];"
        : "=r"(r[0]), "=r"(r[1]), "=r"(r[2]), "=r"(r[3]) : "r"(addr));
}
__device__ __forceinline__ void ldsm4t(uint32_t* r, uint32_t addr) {
    asm volatile("ldmatrix.sync.aligned.m8n8.x4.trans.shared.b16 {%0,%1,%2,%3}, [%4];"
        : "=r"(r[0]), "=r"(r[1]), "=r"(r[2]), "=r"(r[3]) : "r"(addr));
}
__device__ __forceinline__ void mma16816(float* c, const uint32_t* a, const uint32_t* b) {
    asm volatile(
        "mma.sync.aligned.m16n8k16.row.col.f32.bf16.bf16.f32 "
        "{%0,%1,%2,%3}, {%4,%5,%6,%7}, {%8,%9}, {%0,%1,%2,%3};"
        : "+f"(c[0]), "+f"(c[1]), "+f"(c[2]), "+f"(c[3])
        : "r"(a[0]), "r"(a[1]), "r"(a[2]), "r"(a[3]), "r"(b[0]), "r"(b[1]));
}
// two fp32 -> packed bf16x2 hi + bf16x2 lo (residual)
__device__ __forceinline__ void split2(float x, float y, uint32_t& hi, uint32_t& lo) {
    __nv_bfloat162 h = __floats2bfloat162_rn(x, y);
    __nv_bfloat162 l = __floats2bfloat162_rn(x - __low2float(h), y - __high2float(h));
    hi = *reinterpret_cast<uint32_t*>(&h);
    lo = *reinterpret_cast<uint32_t*>(&l);
}

// ---------------------------------------------------------------------------
// Embedding * sqrt(D) + sinusoidal PE (+ hi/lo split)
// ---------------------------------------------------------------------------
__global__ void embed_kernel(const int* __restrict__ src, const float* __restrict__ emb,
                             float* __restrict__ X, __nv_bfloat16* __restrict__ Xh,
                             __nv_bfloat16* __restrict__ Xl)
{
    int row = blockIdx.x;
    int s   = row % Sq;
    int tok = src[row];
    const float* er = emb + (size_t)tok * Dm;
    size_t base = (size_t)row * Dm;
    #pragma unroll
    for (int e = 0; e < 4; e++) {
        int d  = threadIdx.x + e * 256;
        int j2 = (d >> 1) * 2;
        float div = powf(10000.0f, (float)j2 / (float)Dm);
        float ang = (float)s / div;
        float pe  = (d & 1) ? cosf(ang) : sinf(ang);
        float v = er[d] * 32.0f + pe;
        X[base + d] = v;
        __nv_bfloat16 h = __float2bfloat16(v);
        Xh[base + d] = h;
        Xl[base + d] = __float2bfloat16(v - __bfloat162float(h));
    }
}

// ---------------------------------------------------------------------------
// Weight transpose + hi/lo split, batched over layers via blockIdx.z
// ---------------------------------------------------------------------------
__global__ __launch_bounds__(256)
void wt_convz_kernel(const float* __restrict__ W, __nv_bfloat16* __restrict__ Thi,
                     __nv_bfloat16* __restrict__ Tlo, int K, int N,
                     size_t src_stride, size_t dst_stride)
{
    int l = blockIdx.z;
    W   += (size_t)l * src_stride;
    Thi += (size_t)l * dst_stride;
    Tlo += (size_t)l * dst_stride;
    __shared__ float t[32][33];
    int n0 = blockIdx.x * 32, k0 = blockIdx.y * 32;
    int tx = threadIdx.x & 31, ty = threadIdx.x >> 5;
    #pragma unroll
    for (int j = 0; j < 4; j++)
        t[ty + j*8][tx] = W[(size_t)(k0 + ty + j*8) * N + n0 + tx];
    __syncthreads();
    #pragma unroll
    for (int j = 0; j < 4; j++) {
        float v = t[tx][ty + j*8];
        __nv_bfloat16 h = __float2bfloat16(v);
        __nv_bfloat16 lo = __float2bfloat16(v - __bfloat162float(h));
        size_t idx = (size_t)(n0 + ty + j*8) * K + k0 + tx;
        Thi[idx] = h; Tlo[idx] = lo;
    }
}

__global__ void pack_bias_kernel(const float* __restrict__ bq, const float* __restrict__ bk,
                                 const float* __restrict__ bv, float* __restrict__ dst)
{
    int idx = blockIdx.x * 256 + threadIdx.x;
    int l = idx / (3*Dm), j = idx % (3*Dm);
    float v = (j < Dm) ? bq[l*Dm + j] : (j < 2*Dm) ? bk[l*Dm + j - Dm] : bv[l*Dm + j - 2*Dm];
    dst[idx] = v;
}

// ---------------------------------------------------------------------------
// HMMA bf16-split GEMM: C = A @ W + bias (+ReLU)
// 128x256 CTA tile, 512 threads = 16 warps (4M x 4N), warp tile 32x64.
// BK=32 half-unit cp.async ring: 4 slots of 48KB across 2x96KB buffers,
// lookahead 3, wait_group <=2.
// ---------------------------------------------------------------------------
#define G_AH 0
#define G_AL 16384
#define G_BH 32768
#define G_BL 65536
#define STAGEB 98304
#define GEMM_SMEM (2*STAGEB)      /* 196608 */

__device__ __forceinline__ void load_unit(
    uint32_t sb, const __nv_bfloat16* Ahi, const __nv_bfloat16* Alo,
    const __nv_bfloat16* Bhi, const __nv_bfloat16* Blo,
    int bm, int bn, int K, int u, int tid)
{
    uint32_t stg = sb + (((u >> 1) & 1) ? STAGEB : 0);
    int h = u & 1;
    size_t kg = (size_t)u * 32;
    // A tiles: 128 rows x 4 chunks (hi + lo); 512 entries, one per thread
    {
        int row = tid >> 2, cl = tid & 3;
        int chunk = 4 * h + cl;
        uint32_t off = row * 128 + ((chunk ^ (row & 7)) << 4);
        const void* gh = Ahi + (size_t)(bm + row) * K + kg + cl * 8;
        const void* gl = Alo + (size_t)(bm + row) * K + kg + cl * 8;
        asm volatile("cp.async.cg.shared.global [%0], [%1], 16;" :: "r"(stg + G_AH + off), "l"(gh));
        asm volatile("cp.async.cg.shared.global [%0], [%1], 16;" :: "r"(stg + G_AL + off), "l"(gl));
    }
    // B tiles: 256 rows x 4 chunks (hi + lo); 1024 entries
    #pragma unroll
    for (int i = 0; i < 2; i++) {
        int idx = tid + i * 512;
        int row = idx >> 2, cl = idx & 3;
        int chunk = 4 * h + cl;
        uint32_t off = row * 128 + ((chunk ^ (row & 7)) << 4);
        const void* gh = Bhi + (size_t)(bn + row) * K + kg + cl * 8;
        const void* gl = Blo + (size_t)(bn + row) * K + kg + cl * 8;
        asm volatile("cp.async.cg.shared.global [%0], [%1], 16;" :: "r"(stg + G_BH + off), "l"(gh));
        asm volatile("cp.async.cg.shared.global [%0], [%1], 16;" :: "r"(stg + G_BL + off), "l"(gl));
    }
    asm volatile("cp.async.commit_group;" ::: "memory");
}

__global__ __launch_bounds__(512, 1)
void gemm_tc_kernel(const __nv_bfloat16* __restrict__ Ahi, const __nv_bfloat16* __restrict__ Alo,
                    const __nv_bfloat16* __restrict__ Bhi, const __nv_bfloat16* __restrict__ Blo,
                    const float* __restrict__ bias, float* __restrict__ Cf,
                    __nv_bfloat16* __restrict__ Chi, __nv_bfloat16* __restrict__ Clo,
                    int M, int N, int K, int relu)
{
    extern __shared__ __align__(1024) char smem[];
    uint32_t sb  = smem_u32(smem);
    int tid = threadIdx.x, wid = tid >> 5, lane = tid & 31;
    int bn = blockIdx.x * 256, bm = blockIdx.y * 128;
    int KU = K >> 5;    // K32 units

    int m0 = (wid & 3) * 32;     // warp M base (4 warps over 128 rows)
    int n0 = (wid >> 2) * 64;    // warp N base (4 warps over 256 cols)

    float acc[2][8][4];
    #pragma unroll
    for (int a = 0; a < 2; a++)
        #pragma unroll
        for (int b = 0; b < 8; b++)
            #pragma unroll
            for (int c = 0; c < 4; c++) acc[a][b][c] = 0.f;

    load_unit(sb, Ahi, Alo, Bhi, Blo, bm, bn, K, 0, tid);
    load_unit(sb, Ahi, Alo, Bhi, Blo, bm, bn, K, 1, tid);
    load_unit(sb, Ahi, Alo, Bhi, Blo, bm, bn, K, 2, tid);

    int a_ri = ((lane >> 3) & 1) * 8 + (lane & 7);
    int a_ci = (lane >> 4);
    int b_ri = ((lane >> 4) << 3) + (lane & 7);
    int b_ci = ((lane >> 3) & 1);

    for (int u = 0; u < KU; u++) {
        int rem = KU - 1 - u;
        if (rem >= 2)      asm volatile("cp.async.wait_group 2;" ::: "memory");
        else if (rem == 1) asm volatile("cp.async.wait_group 1;" ::: "memory");
        else               asm volatile("cp.async.wait_group 0;" ::: "memory");
        __syncthreads();

        if (u + 3 < KU)
            load_unit(sb, Ahi, Alo, Bhi, Blo, bm, bn, K, u + 3, tid);

        uint32_t stg = sb + (((u >> 1) & 1) ? STAGEB : 0);
        int h = u & 1;

        #pragma unroll
        for (int ksl = 0; ksl < 2; ksl++) {
            int cbase = 4 * h + 2 * ksl;
            uint32_t aH[2][4], aL[2][4];
            int achk = cbase + a_ci;
            #pragma unroll
            for (int mf = 0; mf < 2; mf++) {
                int row = m0 + mf * 16 + a_ri;
                uint32_t off = row * 128 + ((achk ^ (row & 7)) << 4);
                ldsm4(aH[mf], stg + G_AH + off);
                ldsm4(aL[mf], stg + G_AL + off);
            }
            int bchk = cbase + b_ci;
            #pragma unroll
            for (int g = 0; g < 4; g++) {
                int row = n0 + g * 16 + b_ri;
                uint32_t off = row * 128 + ((bchk ^ (row & 7)) << 4);
                uint32_t tH[4], tL[4];
                ldsm4(tH, stg + G_BH + off);
                ldsm4(tL, stg + G_BL + off);
                #pragma unroll
                for (int mf = 0; mf < 2; mf++) {
                    mma16816(acc[mf][2*g],   aH[mf], tH);
                    mma16816(acc[mf][2*g],   aL[mf], tH);
                    mma16816(acc[mf][2*g],   aH[mf], tL);
                    mma16816(acc[mf][2*g+1], aH[mf], tH + 2);
                    mma16816(acc[mf][2*g+1], aL[mf], tH + 2);
                    mma16816(acc[mf][2*g+1], aH[mf], tL + 2);
                }
            }
        }
    }

    int lrow = lane >> 2, lcol = (lane & 3) * 2;
    #pragma unroll
    for (int mf = 0; mf < 2; mf++) {
        int row = bm + m0 + mf * 16 + lrow;
        #pragma unroll
        for (int nf = 0; nf < 8; nf++) {
            int col = bn + n0 + nf * 8 + lcol;
            float b0 = bias[col], b1 = bias[col + 1];
            float2 v0, v1;
            v0.x = acc[mf][nf][0] + b0; v0.y = acc[mf][nf][1] + b1;
            v1.x = acc[mf][nf][2] + b0; v1.y = acc[mf][nf][3] + b1;
            if (relu) {
                v0.x = fmaxf(v0.x, 0.f); v0.y = fmaxf(v0.y, 0.f);
                v1.x = fmaxf(v1.x, 0.f); v1.y = fmaxf(v1.y, 0.f);
            }
            if (Cf) {
                *(float2*)(Cf + (size_t)row * N + col)       = v0;
                *(float2*)(Cf + (size_t)(row + 8) * N + col) = v1;
            }
            if (Chi) {
                uint32_t h0, l0u, h1, l1u;
                split2(v0.x, v0.y, h0, l0u);
                split2(v1.x, v1.y, h1, l1u);
                *(uint32_t*)(Chi + (size_t)row * N + col)       = h0;
                *(uint32_t*)(Clo + (size_t)row * N + col)       = l0u;
                *(uint32_t*)(Chi + (size_t)(row + 8) * N + col) = h1;
                *(uint32_t*)(Clo + (size_t)(row + 8) * N + col) = l1u;
            }
        }
    }
}

// ---------------------------------------------------------------------------
// Tensor-core flash attention (bf16 hi/lo split, fp32 accum)
// ---------------------------------------------------------------------------
#define A_QH 0
#define A_QL 16384
#define A_ST 32768
#define A_MSK 163840
#define ATTN_SMEM (163840 + 4096)

__device__ __forceinline__ void attn_load_tile(uint32_t dst, const __nv_bfloat16* src,
                                               size_t row0, int colbase, int tid)
{
    #pragma unroll
    for (int i = 0; i < 4; i++) {
        int c = tid + i * 256;
        int row = c >> 3, cb = c & 7;
        uint32_t d = dst + row * 128 + ((cb ^ (row & 7)) << 4);
        const void* gp = src + (row0 + row) * (size_t)(3 * Dm) + colbase + cb * 8;
        asm volatile("cp.async.cg.shared.global [%0], [%1], 16;" :: "r"(d), "l"(gp));
    }
}

__global__ __launch_bounds__(256, 1)
void attn_tc_kernel(const __nv_bfloat16* __restrict__ QKVh, const __nv_bfloat16* __restrict__ QKVl,
                    const int* __restrict__ mask, __nv_bfloat16* __restrict__ Oh,
                    __nv_bfloat16* __restrict__ Ol)
{
    extern __shared__ __align__(1024) char smem[];
    uint32_t sb = smem_u32(smem);
    int tid = threadIdx.x, wid = tid >> 5, lane = tid & 31;
    int q0 = blockIdx.x * 128, h = blockIdx.y, b = blockIdx.z;

    int* msm = (int*)(smem + A_MSK);
    #pragma unroll
    for (int i = 0; i < 4; i++) msm[tid + i * 256] = mask[b * Sq + tid + i * 256];

    size_t rowQ = (size_t)b * Sq + q0;
    attn_load_tile(sb + A_QH, QKVh, rowQ, h * HDim, tid);
    attn_load_tile(sb + A_QL, QKVl, rowQ, h * HDim, tid);
    asm volatile("cp.async.commit_group;" ::: "memory");
    size_t rowK = (size_t)b * Sq;
    attn_load_tile(sb + A_ST,         QKVh, rowK, Dm + h * HDim, tid);
    attn_load_tile(sb + A_ST + 16384, QKVl, rowK, Dm + h * HDim, tid);
    attn_load_tile(sb + A_ST + 32768, QKVh, rowK, 2 * Dm + h * HDim, tid);
    attn_load_tile(sb + A_ST + 49152, QKVl, rowK, 2 * Dm + h * HDim, tid);
    asm volatile("cp.async.commit_group;" ::: "memory");

    float m0 = -1e30f, m1 = -1e30f, l0 = 0.f, l1 = 0.f;
    float acc[8][4];
    #pragma unroll
    for (int o = 0; o < 8; o++)
        #pragma unroll
        for (int e = 0; e < 4; e++) acc[o][e] = 0.f;

    int a_ri = ((lane >> 3) & 1) * 8 + (lane & 7);
    int a_ci = (lane >> 4);
    int b_ri = ((lane >> 4) << 3) + (lane & 7);
    int b_ci = ((lane >> 3) & 1);

    for (int c = 0; c < 8; c++) {
        if (c < 7) {
            uint32_t stg = sb + A_ST + ((c + 1) & 1) * 65536;
            size_t rk = (size_t)b * Sq + (c + 1) * 128;
            attn_load_tile(stg,         QKVh, rk, Dm + h * HDim, tid);
            attn_load_tile(stg + 16384, QKVl, rk, Dm + h * HDim, tid);
            attn_load_tile(stg + 32768, QKVh, rk, 2 * Dm + h * HDim, tid);
            attn_load_tile(stg + 49152, QKVl, rk, 2 * Dm + h * HDim, tid);
            asm volatile("cp.async.commit_group;" ::: "memory");
            asm volatile("cp.async.wait_group 1;" ::: "memory");
        } else {
            asm volatile("cp.async.wait_group 0;" ::: "memory");
        }
        __syncthreads();

        uint32_t stg = sb + A_ST + (c & 1) * 65536;
        uint32_t KH = stg, KL = stg + 16384, VH = stg + 32768, VL = stg + 49152;

        float s[16][4];
        #pragma unroll
        for (int nf = 0; nf < 16; nf++)
            #pragma unroll
            for (int e = 0; e < 4; e++) s[nf][e] = 0.f;

        #pragma unroll
        for (int ks = 0; ks < 4; ks++) {
            uint32_t aH[4], aL[4];
            int qrow = wid * 16 + a_ri;
            uint32_t aoff = qrow * 128 + (((ks * 2 + a_ci) ^ (qrow & 7)) << 4);
            ldsm4(aH, sb + A_QH + aoff);
            ldsm4(aL, sb + A_QL + aoff);
            #pragma unroll
            for (int g = 0; g < 8; g++) {
                int krow = g * 16 + b_ri;
                uint32_t boff = krow * 128 + (((ks * 2 + b_ci) ^ (krow & 7)) << 4);
                uint32_t tH[4], tL[4];
                ldsm4(tH, KH + boff);
                ldsm4(tL, KL + boff);
                mma16816(s[2*g],   aH, tH);
                mma16816(s[2*g],   aL, tH);
                mma16816(s[2*g],   aH, tL);
                mma16816(s[2*g+1], aH, tH + 2);
                mma16816(s[2*g+1], aL, tH + 2);
                mma16816(s[2*g+1], aH, tL + 2);
            }
        }

        int k0c = c * 128;
        #pragma unroll
        for (int nf = 0; nf < 16; nf++) {
            int col = k0c + nf * 8 + (lane & 3) * 2;
            float ad0 = (msm[col]     == 0) ? -1e10f : 0.f;
            float ad1 = (msm[col + 1] == 0) ? -1e10f : 0.f;
            s[nf][0] = s[nf][0] * 0.125f + ad0;
            s[nf][1] = s[nf][1] * 0.125f + ad1;
            s[nf][2] = s[nf][2] * 0.125f + ad0;
            s[nf][3] = s[nf][3] * 0.125f + ad1;
        }

        float tm0 = -1e30f, tm1 = -1e30f;
        #pragma unroll
        for (int nf = 0; nf < 16; nf++) {
            tm0 = fmaxf(tm0, fmaxf(s[nf][0], s[nf][1]));
            tm1 = fmaxf(tm1, fmaxf(s[nf][2], s[nf][3]));
        }
        tm0 = fmaxf(tm0, __shfl_xor_sync(0xffffffffu, tm0, 1));
        tm0 = fmaxf(tm0, __shfl_xor_sync(0xffffffffu, tm0, 2));
        tm1 = fmaxf(tm1, __shfl_xor_sync(0xffffffffu, tm1, 1));
        tm1 = fmaxf(tm1, __shfl_xor_sync(0xffffffffu, tm1, 2));
        float nm0 = fmaxf(m0, tm0), nm1 = fmaxf(m1, tm1);
        float cr0 = __expf(m0 - nm0), cr1 = __expf(m1 - nm1);
        float rs0 = 0.f, rs1 = 0.f;
        #pragma unroll
        for (int nf = 0; nf < 16; nf++) {
            s[nf][0] = __expf(s[nf][0] - nm0); rs0 += s[nf][0];
            s[nf][1] = __expf(s[nf][1] - nm0); rs0 += s[nf][1];
            s[nf][2] = __expf(s[nf][2] - nm1); rs1 += s[nf][2];
            s[nf][3] = __expf(s[nf][3] - nm1); rs1 += s[nf][3];
        }
        rs0 += __shfl_xor_sync(0xffffffffu, rs0, 1);
        rs0 += __shfl_xor_sync(0xffffffffu, rs0, 2);
        rs1 += __shfl_xor_sync(0xffffffffu, rs1, 1);
        rs1 += __shfl_xor_sync(0xffffffffu, rs1, 2);
        l0 = l0 * cr0 + rs0;  l1 = l1 * cr1 + rs1;
        m0 = nm0;  m1 = nm1;
        #pragma unroll
        for (int o = 0; o < 8; o++) {
            acc[o][0] *= cr0; acc[o][1] *= cr0;
            acc[o][2] *= cr1; acc[o][3] *= cr1;
        }

        #pragma unroll
        for (int kp = 0; kp < 8; kp++) {
            uint32_t pH[4], pL[4];
            split2(s[2*kp][0],   s[2*kp][1],   pH[0], pL[0]);
            split2(s[2*kp][2],   s[2*kp][3],   pH[1], pL[1]);
            split2(s[2*kp+1][0], s[2*kp+1][1], pH[2], pL[2]);
            split2(s[2*kp+1][2], s[2*kp+1][3], pH[3], pL[3]);
            int vrow = kp * 16 + (lane & 7) + ((lane >> 3) & 1) * 8;
            int vck  = (lane >> 4);
            #pragma unroll
            for (int vg = 0; vg < 4; vg++) {
                uint32_t off = vrow * 128 + (((vg * 2 + vck) ^ (vrow & 7)) << 4);
                uint32_t tH[4], tL[4];
                ldsm4t(tH, VH + off);
                ldsm4t(tL, VL + off);
                mma16816(acc[2*vg],   pH, tH);
                mma16816(acc[2*vg],   pL, tH);
                mma16816(acc[2*vg],   pH, tL);
                mma16816(acc[2*vg+1], pH, tH + 2);
                mma16816(acc[2*vg+1], pL, tH + 2);
                mma16816(acc[2*vg+1], pH, tL + 2);
            }
        }
        __syncthreads();
    }

    float i0 = 1.f / l0, i1 = 1.f / l1;
    size_t base0 = ((size_t)b * Sq + q0 + wid * 16 + (lane >> 2)) * Dm + h * HDim + (lane & 3) * 2;
    size_t base1 = base0 + (size_t)8 * Dm;
    #pragma unroll
    for (int nf = 0; nf < 8; nf++) {
        uint32_t h0, l0u, h1, l1u;
        split2(acc[nf][0] * i0, acc[nf][1] * i0, h0, l0u);
        split2(acc[nf][2] * i1, acc[nf][3] * i1, h1, l1u);
        *(uint32_t*)(Oh + base0 + nf * 8) = h0;
        *(uint32_t*)(Ol + base0 + nf * 8) = l0u;
        *(uint32_t*)(Oh + base1 + nf * 8) = h1;
        *(uint32_t*)(Ol + base1 + nf * 8) = l1u;
    }
}

// ---------------------------------------------------------------------------
// dst = LayerNorm(x + t) * g + b  (+ optional hi/lo split outputs)
// ---------------------------------------------------------------------------
__device__ __forceinline__ float block_reduce_sum(float v, float* red)
{
    #pragma unroll
    for (int o = 16; o > 0; o >>= 1) v += __shfl_xor_sync(0xffffffffu, v, o);
    int w = threadIdx.x >> 5;
    if ((threadIdx.x & 31) == 0) red[w] = v;
    __syncthreads();
    if (threadIdx.x < 32) {
        float r = (threadIdx.x < 8) ? red[threadIdx.x] : 0.f;
        #pragma unroll
        for (int o = 4; o > 0; o >>= 1) r += __shfl_xor_sync(0xffffffffu, r, o);
        if (threadIdx.x == 0) red[0] = r;
    }
    __syncthreads();
    float r = red[0];
    __syncthreads();
    return r;
}

__global__ __launch_bounds__(256)
void add_ln_kernel(const float* __restrict__ x, const float* __restrict__ t,
                   const float* __restrict__ g, const float* __restrict__ bt,
                   float* __restrict__ dst, __nv_bfloat16* __restrict__ dhi,
                   __nv_bfloat16* __restrict__ dlo)
{
    __shared__ float red[8];
    size_t base = (size_t)blockIdx.x * Dm;
    float v[4]; float s = 0.f;
    #pragma unroll
    for (int e = 0; e < 4; e++) {
        int c = threadIdx.x + e * 256;
        v[e] = x[base + c] + t[base + c];
        s += v[e];
    }
    s = block_reduce_sum(s, red);
    float mu = s * (1.0f / Dm);
    float q = 0.f;
    #pragma unroll
    for (int e = 0; e < 4; e++) { float d = v[e] - mu; q += d * d; }
    q = block_reduce_sum(q, red);
    float inv = rsqrtf(q * (1.0f / Dm) + 1e-5f);
    #pragma unroll
    for (int e = 0; e < 4; e++) {
        int c = threadIdx.x + e * 256;
        float o = (v[e] - mu) * inv * g[c] + bt[c];
        dst[base + c] = o;
        if (dhi) {
            __nv_bfloat16 h = __float2bfloat16(o);
            dhi[base + c] = h;
            dlo[base + c] = __float2bfloat16(o - __bfloat162float(h));
        }
    }
}

// ---------------------------------------------------------------------------
extern "C" void kernel_launch(void* const* d_in, const int* in_sizes, int n_in,
                              void* d_out, int out_size)
{
    const int*   src = (const int*)d_in[0];
    const int*   msk = (const int*)d_in[1];
    const float* emb = (const float*)d_in[2];
    const float* Wq  = (const float*)d_in[3];
    const float* bq  = (const float*)d_in[4];
    const float* Wk  = (const float*)d_in[5];
    const float* bk  = (const float*)d_in[6];
    const float* Wv  = (const float*)d_in[7];
    const float* bv  = (const float*)d_in[8];
    const float* Wo  = (const float*)d_in[9];
    const float* bo  = (const float*)d_in[10];
    const float* g1  = (const float*)d_in[11];
    const float* b1n = (const float*)d_in[12];
    const float* W1  = (const float*)d_in[13];
    const float* b1  = (const float*)d_in[14];
    const float* W2  = (const float*)d_in[15];
    const float* b2  = (const float*)d_in[16];
    const float* g2  = (const float*)d_in[17];
    const float* b2n = (const float*)d_in[18];
    float* out = (float*)d_out;

    float* f32 = nullptr;
    cudaGetSymbolAddress((void**)&f32, g_f32);
    float* X  = f32;
    float* T2 = f32 + (size_t)NTOK * Dm;

    __nv_bfloat16 *Xh, *Xl, *Qh, *Ql, *Ohb, *Olb, *Hh, *Hl, *Wh, *Wl;
    float* bqkv;
    cudaGetSymbolAddress((void**)&Xh,  g_xh);
    cudaGetSymbolAddress((void**)&Xl,  g_xl);
    cudaGetSymbolAddress((void**)&Qh,  g_qkvh);
    cudaGetSymbolAddress((void**)&Ql,  g_qkvl);
    cudaGetSymbolAddress((void**)&Ohb, g_oh);
    cudaGetSymbolAddress((void**)&Olb, g_ol);
    cudaGetSymbolAddress((void**)&Hh,  g_hh);
    cudaGetSymbolAddress((void**)&Hl,  g_hl);
    cudaGetSymbolAddress((void**)&Wh,  g_wt_hi);
    cudaGetSymbolAddress((void**)&Wl,  g_wt_lo);
    cudaGetSymbolAddress((void**)&bqkv, g_bqkv);

    cudaFuncSetAttribute((const void*)gemm_tc_kernel,
                         cudaFuncAttributeMaxDynamicSharedMemorySize, GEMM_SMEM);
    cudaFuncSetAttribute((const void*)attn_tc_kernel,
                         cudaFuncAttributeMaxDynamicSharedMemorySize, ATTN_SMEM);

    const size_t M1  = (size_t)1024 * 1024;
    const size_t LWT = 12 * M1;

    wt_convz_kernel<<<dim3(32, 32, NL), 256>>>(Wq, Wh,          Wl,          Dm, Dm, (size_t)Dm*Dm, LWT);
    wt_convz_kernel<<<dim3(32, 32, NL), 256>>>(Wk, Wh + M1,     Wl + M1,     Dm, Dm, (size_t)Dm*Dm, LWT);
    wt_convz_kernel<<<dim3(32, 32, NL), 256>>>(Wv, Wh + 2*M1,   Wl + 2*M1,   Dm, Dm, (size_t)Dm*Dm, LWT);
    wt_convz_kernel<<<dim3(32, 32, NL), 256>>>(Wo, Wh + 3*M1,   Wl + 3*M1,   Dm, Dm, (size_t)Dm*Dm, LWT);
    wt_convz_kernel<<<dim3(Ff/32, Dm/32, NL), 256>>>(W1, Wh + 4*M1, Wl + 4*M1, Dm, Ff, (size_t)Dm*Ff, LWT);
    wt_convz_kernel<<<dim3(Dm/32, Ff/32, NL), 256>>>(W2, Wh + 8*M1, Wl + 8*M1, Ff, Dm, (size_t)Dm*Ff, LWT);
    pack_bias_kernel<<<NL * 3 * Dm / 256, 256>>>(bq, bk, bv, bqkv);

    embed_kernel<<<NTOK, 256>>>(src, emb, X, Xh, Xl);

    dim3 gQKV(3 * Dm / 256, NTOK / 128);  // (12, 64)
    dim3 gD(Dm / 256, NTOK / 128);        // (4, 64)
    dim3 gF(Ff / 256, NTOK / 128);        // (16, 64)
    dim3 gA(Sq / 128, Hn, Bz);            // (8, 16, 8)

    for (int l = 0; l < NL; l++) {
        size_t oD = (size_t)l * Dm, oF = (size_t)l * Ff;
        size_t wb = (size_t)l * LWT;
        bool last = (l == NL - 1);

        gemm_tc_kernel<<<gQKV, 512, GEMM_SMEM>>>(Xh, Xl, Wh + wb, Wl + wb,
            bqkv + (size_t)l * 3 * Dm, nullptr, Qh, Ql, NTOK, 3 * Dm, Dm, 0);
        attn_tc_kernel<<<gA, 256, ATTN_SMEM>>>(Qh, Ql, msk, Ohb, Olb);
        gemm_tc_kernel<<<gD, 512, GEMM_SMEM>>>(Ohb, Olb, Wh + wb + 3*M1, Wl + wb + 3*M1,
            bo + oD, T2, nullptr, nullptr, NTOK, Dm, Dm, 0);
        add_ln_kernel<<<NTOK, 256>>>(X, T2, g1 + oD, b1n + oD, X, Xh, Xl);
        gemm_tc_kernel<<<gF, 512, GEMM_SMEM>>>(Xh, Xl, Wh + wb + 4*M1, Wl + wb + 4*M1,
            b1 + oF, nullptr, Hh, Hl, NTOK, Ff, Dm, 1);
        gemm_tc_kernel<<<gD, 512, GEMM_SMEM>>>(Hh, Hl, Wh + wb + 8*M1, Wl + wb + 8*M1,
            b2 + oD, T2, nullptr, nullptr, NTOK, Dm, Ff, 0);
        add_ln_kernel<<<NTOK, 256>>>(X, T2, g2 + oD, b2n + oD,
            last ? out : X, last ? nullptr : Xh, Xl);
    }
}

// round 15
// speedup vs baseline: 1.5008x; 1.4962x over previous
#include <cuda_runtime.h>
#include <cuda_fp16.h>
#include <math.h>
#include <stdint.h>

#define Bz   8
#define Sq   1024
#define Dm   1024
#define Hn   16
#define HDim 64
#define Ff   4096
#define NL   6
#define NTOK (Bz*Sq)   /* 8192 tokens */

// fp32 scratch: X, T2
__device__ float g_f32[(size_t)NTOK*Dm*2];
// fp16 hi/lo activation buffers (lo only needed for A-side operands)
__device__ __half g_xh[(size_t)NTOK*Dm],     g_xl[(size_t)NTOK*Dm];
__device__ __half g_qkvh[(size_t)NTOK*3*Dm], g_qkvl[(size_t)NTOK*3*Dm];
__device__ __half g_oh[(size_t)NTOK*Dm],     g_ol[(size_t)NTOK*Dm];
__device__ __half g_hh[(size_t)NTOK*Ff],     g_hl[(size_t)NTOK*Ff];
// fp16 transposed weights (single term): per layer 12M elems
__device__ __half g_wt[(size_t)NL*12*1024*1024];
// packed QKV bias
__device__ float g_bqkv[(size_t)NL*3*Dm];

// ---------------------------------------------------------------------------
// helpers
// ---------------------------------------------------------------------------
__device__ __forceinline__ uint32_t smem_u32(const void* p) {
    uint32_t a;
    asm("{ .reg .u64 t; cvta.to.shared.u64 t, %1; cvt.u32.u64 %0, t; }" : "=r"(a) : "l"(p));
    return a;
}
__device__ __forceinline__ void ldsm4(uint32_t* r, uint32_t addr) {
    asm volatile("ldmatrix.sync.aligned.m8n8.x4.shared.b16 {%0,%1,%2,%3}, [%4];"
        : "=r"(r[0]), "=r"(r[1]), "=r"(r[2]), "=r"(r[3]) : "r"(addr));
}
__device__ __forceinline__ void ldsm4t(uint32_t* r, uint32_t addr) {
    asm volatile("ldmatrix.sync.aligned.m8n8.x4.trans.shared.b16 {%0,%1,%2,%3}, [%4];"
        : "=r"(r[0]), "=r"(r[1]), "=r"(r[2]), "=r"(r[3]) : "r"(addr));
}
__device__ __forceinline__ void mma16816(float* c, const uint32_t* a, const uint32_t* b) {
    asm volatile(
        "mma.sync.aligned.m16n8k16.row.col.f32.f16.f16.f32 "
        "{%0,%1,%2,%3}, {%4,%5,%6,%7}, {%8,%9}, {%0,%1,%2,%3};"
        : "+f"(c[0]), "+f"(c[1]), "+f"(c[2]), "+f"(c[3])
        : "r"(a[0]), "r"(a[1]), "r"(a[2]), "r"(a[3]), "r"(b[0]), "r"(b[1]));
}
// two fp32 -> packed fp16x2 hi + fp16x2 lo (residual)
__device__ __forceinline__ void split2(float x, float y, uint32_t& hi, uint32_t& lo) {
    __half2 h = __floats2half2_rn(x, y);
    __half2 l = __floats2half2_rn(x - __low2float(h), y - __high2float(h));
    hi = *reinterpret_cast<uint32_t*>(&h);
    lo = *reinterpret_cast<uint32_t*>(&l);
}

// ---------------------------------------------------------------------------
// Embedding * sqrt(D) + sinusoidal PE (+ hi/lo split)
// ---------------------------------------------------------------------------
__global__ void embed_kernel(const int* __restrict__ src, const float* __restrict__ emb,
                             float* __restrict__ X, __half* __restrict__ Xh,
                             __half* __restrict__ Xl)
{
    int row = blockIdx.x;
    int s   = row % Sq;
    int tok = src[row];
    const float* er = emb + (size_t)tok * Dm;
    size_t base = (size_t)row * Dm;
    #pragma unroll
    for (int e = 0; e < 4; e++) {
        int d  = threadIdx.x + e * 256;
        int j2 = (d >> 1) * 2;
        float div = powf(10000.0f, (float)j2 / (float)Dm);
        float ang = (float)s / div;
        float pe  = (d & 1) ? cosf(ang) : sinf(ang);
        float v = er[d] * 32.0f + pe;
        X[base + d] = v;
        __half h = __float2half_rn(v);
        Xh[base + d] = h;
        Xl[base + d] = __float2half_rn(v - __half2float(h));
    }
}

// ---------------------------------------------------------------------------
// Weight transpose + fp16 convert, batched over layers via blockIdx.z
// W[K,N] fp32 -> T[N,K] fp16
// ---------------------------------------------------------------------------
__global__ __launch_bounds__(256)
void wt_convz_kernel(const float* __restrict__ W, __half* __restrict__ T,
                     int K, int N, size_t src_stride, size_t dst_stride)
{
    int l = blockIdx.z;
    W += (size_t)l * src_stride;
    T += (size_t)l * dst_stride;
    __shared__ float t[32][33];
    int n0 = blockIdx.x * 32, k0 = blockIdx.y * 32;
    int tx = threadIdx.x & 31, ty = threadIdx.x >> 5;
    #pragma unroll
    for (int j = 0; j < 4; j++)
        t[ty + j*8][tx] = W[(size_t)(k0 + ty + j*8) * N + n0 + tx];
    __syncthreads();
    #pragma unroll
    for (int j = 0; j < 4; j++) {
        float v = t[tx][ty + j*8];
        T[(size_t)(n0 + ty + j*8) * K + k0 + tx] = __float2half_rn(v);
    }
}

__global__ void pack_bias_kernel(const float* __restrict__ bq, const float* __restrict__ bk,
                                 const float* __restrict__ bv, float* __restrict__ dst)
{
    int idx = blockIdx.x * 256 + threadIdx.x;
    int l = idx / (3*Dm), j = idx % (3*Dm);
    float v = (j < Dm) ? bq[l*Dm + j] : (j < 2*Dm) ? bk[l*Dm + j - Dm] : bv[l*Dm + j - 2*Dm];
    dst[idx] = v;
}

// ---------------------------------------------------------------------------
// HMMA fp16 2-term GEMM: C = (Ahi+Alo) @ B + bias (+ReLU)
// 128x128 CTA tile, 8 warps (2M x 4N), warp tile 64x32, BK=64,
// 4-stage cp.async ring (3 tiles/stage: AH, AL, BH).
// ---------------------------------------------------------------------------
#define G_AH 0
#define G_AL 16384
#define G_BH 32768
#define STAGEB 49152
#define NSTAGE 4
#define GEMM_SMEM (NSTAGE*STAGEB)   /* 196608 */

__device__ __forceinline__ void load_stage3(
    uint32_t stage, const __half* Ahi, const __half* Alo, const __half* Bh,
    int bm, int bn, int K, int k0, int tid)
{
    #pragma unroll
    for (int i = 0; i < 4; i++) {
        int c = tid + i * 256;        // 1024 16B chunks per tile
        int row = c >> 3, cb = c & 7;
        uint32_t off = row * 128 + ((cb ^ (row & 7)) << 4);
        const void* ga = Ahi + (size_t)(bm + row) * K + k0 + cb * 8;
        const void* gl = Alo + (size_t)(bm + row) * K + k0 + cb * 8;
        const void* gb = Bh  + (size_t)(bn + row) * K + k0 + cb * 8;
        asm volatile("cp.async.cg.shared.global [%0], [%1], 16;" :: "r"(stage + G_AH + off), "l"(ga));
        asm volatile("cp.async.cg.shared.global [%0], [%1], 16;" :: "r"(stage + G_AL + off), "l"(gl));
        asm volatile("cp.async.cg.shared.global [%0], [%1], 16;" :: "r"(stage + G_BH + off), "l"(gb));
    }
    asm volatile("cp.async.commit_group;" ::: "memory");
}

__global__ __launch_bounds__(256, 1)
void gemm_tc_kernel(const __half* __restrict__ Ahi, const __half* __restrict__ Alo,
                    const __half* __restrict__ Bh,
                    const float* __restrict__ bias, float* __restrict__ Cf,
                    __half* __restrict__ Chi, __half* __restrict__ Clo,
                    int M, int N, int K, int relu)
{
    extern __shared__ __align__(1024) char smem[];
    uint32_t sb  = smem_u32(smem);
    int tid = threadIdx.x, wid = tid >> 5, lane = tid & 31;
    int bn = blockIdx.x * 128, bm = blockIdx.y * 128;
    int KSTEPS = K >> 6;

    int r0 = (wid & 1) * 64;
    int n0 = (wid >> 1) * 32;

    float acc[4][4][4];
    #pragma unroll
    for (int a = 0; a < 4; a++)
        #pragma unroll
        for (int b = 0; b < 4; b++)
            #pragma unroll
            for (int c = 0; c < 4; c++) acc[a][b][c] = 0.f;

    load_stage3(sb,            Ahi, Alo, Bh, bm, bn, K, 0,   tid);
    load_stage3(sb + STAGEB,   Ahi, Alo, Bh, bm, bn, K, 64,  tid);
    load_stage3(sb + 2*STAGEB, Ahi, Alo, Bh, bm, bn, K, 128, tid);

    int a_ri = ((lane >> 3) & 1) * 8 + (lane & 7);
    int a_ci = (lane >> 4);
    int b_ri = ((lane >> 4) << 3) + (lane & 7);
    int b_ci = ((lane >> 3) & 1);

    for (int it = 0; it < KSTEPS; it++) {
        int rem = KSTEPS - 1 - it;
        if (rem >= 2)      asm volatile("cp.async.wait_group 2;" ::: "memory");
        else if (rem == 1) asm volatile("cp.async.wait_group 1;" ::: "memory");
        else               asm volatile("cp.async.wait_group 0;" ::: "memory");
        __syncthreads();

        if (it + 3 < KSTEPS)
            load_stage3(sb + ((it + 3) & 3) * STAGEB, Ahi, Alo, Bh, bm, bn, K,
                        (it + 3) * 64, tid);

        uint32_t stg = sb + (it & 3) * STAGEB;

        #pragma unroll
        for (int ks = 0; ks < 4; ks++) {
            uint32_t aH[4][4], aL[4][4];
            int achk = 2 * ks + a_ci;
            #pragma unroll
            for (int mf = 0; mf < 4; mf++) {
                int row = r0 + mf * 16 + a_ri;
                uint32_t off = row * 128 + ((achk ^ (row & 7)) << 4);
                ldsm4(aH[mf], stg + G_AH + off);
                ldsm4(aL[mf], stg + G_AL + off);
            }
            int bchk = 2 * ks + b_ci;
            #pragma unroll
            for (int g = 0; g < 2; g++) {
                int row = n0 + g * 16 + b_ri;
                uint32_t off = row * 128 + ((bchk ^ (row & 7)) << 4);
                uint32_t tH[4];
                ldsm4(tH, stg + G_BH + off);
                #pragma unroll
                for (int mf = 0; mf < 4; mf++) {
                    mma16816(acc[mf][2*g],   aH[mf], tH);
                    mma16816(acc[mf][2*g],   aL[mf], tH);
                    mma16816(acc[mf][2*g+1], aH[mf], tH + 2);
                    mma16816(acc[mf][2*g+1], aL[mf], tH + 2);
                }
            }
        }
    }

    int lrow = lane >> 2, lcol = (lane & 3) * 2;
    #pragma unroll
    for (int mf = 0; mf < 4; mf++) {
        int row = bm + r0 + mf * 16 + lrow;
        #pragma unroll
        for (int nf = 0; nf < 4; nf++) {
            int col = bn + n0 + nf * 8 + lcol;
            float b0 = bias[col], b1 = bias[col + 1];
            float2 v0, v1;
            v0.x = acc[mf][nf][0] + b0; v0.y = acc[mf][nf][1] + b1;
            v1.x = acc[mf][nf][2] + b0; v1.y = acc[mf][nf][3] + b1;
            if (relu) {
                v0.x = fmaxf(v0.x, 0.f); v0.y = fmaxf(v0.y, 0.f);
                v1.x = fmaxf(v1.x, 0.f); v1.y = fmaxf(v1.y, 0.f);
            }
            if (Cf) {
                *(float2*)(Cf + (size_t)row * N + col)       = v0;
                *(float2*)(Cf + (size_t)(row + 8) * N + col) = v1;
            }
            if (Chi) {
                uint32_t h0, l0u, h1, l1u;
                split2(v0.x, v0.y, h0, l0u);
                split2(v1.x, v1.y, h1, l1u);
                *(uint32_t*)(Chi + (size_t)row * N + col)       = h0;
                *(uint32_t*)(Clo + (size_t)row * N + col)       = l0u;
                *(uint32_t*)(Chi + (size_t)(row + 8) * N + col) = h1;
                *(uint32_t*)(Clo + (size_t)(row + 8) * N + col) = l1u;
            }
        }
    }
}

// ---------------------------------------------------------------------------
// Tensor-core flash attention (fp16: Q 2-term, K/V 1-term, fp32 accum)
// block = (128 q rows, head, batch); 8 warps x 16 q rows
// ---------------------------------------------------------------------------
#define A_QH 0
#define A_QL 16384
#define A_ST 32768          /* stage s at A_ST + s*32768: KH, VH (16KB each) */
#define A_MSK 98304
#define ATTN_SMEM (98304 + 4096)

__device__ __forceinline__ void attn_load_tile(uint32_t dst, const __half* src,
                                               size_t row0, int colbase, int tid)
{
    #pragma unroll
    for (int i = 0; i < 4; i++) {
        int c = tid + i * 256;
        int row = c >> 3, cb = c & 7;
        uint32_t d = dst + row * 128 + ((cb ^ (row & 7)) << 4);
        const void* gp = src + (row0 + row) * (size_t)(3 * Dm) + colbase + cb * 8;
        asm volatile("cp.async.cg.shared.global [%0], [%1], 16;" :: "r"(d), "l"(gp));
    }
}

__global__ __launch_bounds__(256, 1)
void attn_tc_kernel(const __half* __restrict__ QKVh, const __half* __restrict__ QKVl,
                    const int* __restrict__ mask, __half* __restrict__ Oh,
                    __half* __restrict__ Ol)
{
    extern __shared__ __align__(1024) char smem[];
    uint32_t sb = smem_u32(smem);
    int tid = threadIdx.x, wid = tid >> 5, lane = tid & 31;
    int q0 = blockIdx.x * 128, h = blockIdx.y, b = blockIdx.z;

    int* msm = (int*)(smem + A_MSK);
    #pragma unroll
    for (int i = 0; i < 4; i++) msm[tid + i * 256] = mask[b * Sq + tid + i * 256];

    size_t rowQ = (size_t)b * Sq + q0;
    attn_load_tile(sb + A_QH, QKVh, rowQ, h * HDim, tid);
    attn_load_tile(sb + A_QL, QKVl, rowQ, h * HDim, tid);
    asm volatile("cp.async.commit_group;" ::: "memory");
    size_t rowK = (size_t)b * Sq;
    attn_load_tile(sb + A_ST,         QKVh, rowK, Dm + h * HDim, tid);
    attn_load_tile(sb + A_ST + 16384, QKVh, rowK, 2 * Dm + h * HDim, tid);
    asm volatile("cp.async.commit_group;" ::: "memory");

    float m0 = -1e30f, m1 = -1e30f, l0 = 0.f, l1 = 0.f;
    float acc[8][4];
    #pragma unroll
    for (int o = 0; o < 8; o++)
        #pragma unroll
        for (int e = 0; e < 4; e++) acc[o][e] = 0.f;

    int a_ri = ((lane >> 3) & 1) * 8 + (lane & 7);
    int a_ci = (lane >> 4);
    int b_ri = ((lane >> 4) << 3) + (lane & 7);
    int b_ci = ((lane >> 3) & 1);

    for (int c = 0; c < 8; c++) {
        if (c < 7) {
            uint32_t stg = sb + A_ST + ((c + 1) & 1) * 32768;
            size_t rk = (size_t)b * Sq + (c + 1) * 128;
            attn_load_tile(stg,         QKVh, rk, Dm + h * HDim, tid);
            attn_load_tile(stg + 16384, QKVh, rk, 2 * Dm + h * HDim, tid);
            asm volatile("cp.async.commit_group;" ::: "memory");
            asm volatile("cp.async.wait_group 1;" ::: "memory");
        } else {
            asm volatile("cp.async.wait_group 0;" ::: "memory");
        }
        __syncthreads();

        uint32_t stg = sb + A_ST + (c & 1) * 32768;
        uint32_t KH = stg, VH = stg + 16384;

        float s[16][4];
        #pragma unroll
        for (int nf = 0; nf < 16; nf++)
            #pragma unroll
            for (int e = 0; e < 4; e++) s[nf][e] = 0.f;

        #pragma unroll
        for (int ks = 0; ks < 4; ks++) {
            uint32_t aH[4], aL[4];
            int qrow = wid * 16 + a_ri;
            uint32_t aoff = qrow * 128 + (((ks * 2 + a_ci) ^ (qrow & 7)) << 4);
            ldsm4(aH, sb + A_QH + aoff);
            ldsm4(aL, sb + A_QL + aoff);
            #pragma unroll
            for (int g = 0; g < 8; g++) {
                int krow = g * 16 + b_ri;
                uint32_t boff = krow * 128 + (((ks * 2 + b_ci) ^ (krow & 7)) << 4);
                uint32_t tH[4];
                ldsm4(tH, KH + boff);
                mma16816(s[2*g],   aH, tH);
                mma16816(s[2*g],   aL, tH);
                mma16816(s[2*g+1], aH, tH + 2);
                mma16816(s[2*g+1], aL, tH + 2);
            }
        }

        int k0c = c * 128;
        #pragma unroll
        for (int nf = 0; nf < 16; nf++) {
            int col = k0c + nf * 8 + (lane & 3) * 2;
            float ad0 = (msm[col]     == 0) ? -1e10f : 0.f;
            float ad1 = (msm[col + 1] == 0) ? -1e10f : 0.f;
            s[nf][0] = s[nf][0] * 0.125f + ad0;
            s[nf][1] = s[nf][1] * 0.125f + ad1;
            s[nf][2] = s[nf][2] * 0.125f + ad0;
            s[nf][3] = s[nf][3] * 0.125f + ad1;
        }

        float tm0 = -1e30f, tm1 = -1e30f;
        #pragma unroll
        for (int nf = 0; nf < 16; nf++) {
            tm0 = fmaxf(tm0, fmaxf(s[nf][0], s[nf][1]));
            tm1 = fmaxf(tm1, fmaxf(s[nf][2], s[nf][3]));
        }
        tm0 = fmaxf(tm0, __shfl_xor_sync(0xffffffffu, tm0, 1));
        tm0 = fmaxf(tm0, __shfl_xor_sync(0xffffffffu, tm0, 2));
        tm1 = fmaxf(tm1, __shfl_xor_sync(0xffffffffu, tm1, 1));
        tm1 = fmaxf(tm1, __shfl_xor_sync(0xffffffffu, tm1, 2));
        float nm0 = fmaxf(m0, tm0), nm1 = fmaxf(m1, tm1);
        float cr0 = __expf(m0 - nm0), cr1 = __expf(m1 - nm1);
        float rs0 = 0.f, rs1 = 0.f;
        #pragma unroll
        for (int nf = 0; nf < 16; nf++) {
            s[nf][0] = __expf(s[nf][0] - nm0); rs0 += s[nf][0];
            s[nf][1] = __expf(s[nf][1] - nm0); rs0 += s[nf][1];
            s[nf][2] = __expf(s[nf][2] - nm1); rs1 += s[nf][2];
            s[nf][3] = __expf(s[nf][3] - nm1); rs1 += s[nf][3];
        }
        rs0 += __shfl_xor_sync(0xffffffffu, rs0, 1);
        rs0 += __shfl_xor_sync(0xffffffffu, rs0, 2);
        rs1 += __shfl_xor_sync(0xffffffffu, rs1, 1);
        rs1 += __shfl_xor_sync(0xffffffffu, rs1, 2);
        l0 = l0 * cr0 + rs0;  l1 = l1 * cr1 + rs1;
        m0 = nm0;  m1 = nm1;
        #pragma unroll
        for (int o = 0; o < 8; o++) {
            acc[o][0] *= cr0; acc[o][1] *= cr0;
            acc[o][2] *= cr1; acc[o][3] *= cr1;
        }

        #pragma unroll
        for (int kp = 0; kp < 8; kp++) {
            uint32_t pH[4], pL[4];
            split2(s[2*kp][0],   s[2*kp][1],   pH[0], pL[0]);
            split2(s[2*kp][2],   s[2*kp][3],   pH[1], pL[1]);
            split2(s[2*kp+1][0], s[2*kp+1][1], pH[2], pL[2]);
            split2(s[2*kp+1][2], s[2*kp+1][3], pH[3], pL[3]);
            int vrow = kp * 16 + (lane & 7) + ((lane >> 3) & 1) * 8;
            int vck  = (lane >> 4);
            #pragma unroll
            for (int vg = 0; vg < 4; vg++) {
                uint32_t off = vrow * 128 + (((vg * 2 + vck) ^ (vrow & 7)) << 4);
                uint32_t tH[4];
                ldsm4t(tH, VH + off);
                mma16816(acc[2*vg],   pH, tH);
                mma16816(acc[2*vg],   pL, tH);
                mma16816(acc[2*vg+1], pH, tH + 2);
                mma16816(acc[2*vg+1], pL, tH + 2);
            }
        }
        __syncthreads();
    }

    float i0 = 1.f / l0, i1 = 1.f / l1;
    size_t base0 = ((size_t)b * Sq + q0 + wid * 16 + (lane >> 2)) * Dm + h * HDim + (lane & 3) * 2;
    size_t base1 = base0 + (size_t)8 * Dm;
    #pragma unroll
    for (int nf = 0; nf < 8; nf++) {
        uint32_t h0, l0u, h1, l1u;
        split2(acc[nf][0] * i0, acc[nf][1] * i0, h0, l0u);
        split2(acc[nf][2] * i1, acc[nf][3] * i1, h1, l1u);
        *(uint32_t*)(Oh + base0 + nf * 8) = h0;
        *(uint32_t*)(Ol + base0 + nf * 8) = l0u;
        *(uint32_t*)(Oh + base1 + nf * 8) = h1;
        *(uint32_t*)(Ol + base1 + nf * 8) = l1u;
    }
}

// ---------------------------------------------------------------------------
// dst = LayerNorm(x + t) * g + b  (+ optional hi/lo split outputs)
// ---------------------------------------------------------------------------
__device__ __forceinline__ float block_reduce_sum(float v, float* red)
{
    #pragma unroll
    for (int o = 16; o > 0; o >>= 1) v += __shfl_xor_sync(0xffffffffu, v, o);
    int w = threadIdx.x >> 5;
    if ((threadIdx.x & 31) == 0) red[w] = v;
    __syncthreads();
    if (threadIdx.x < 32) {
        float r = (threadIdx.x < 8) ? red[threadIdx.x] : 0.f;
        #pragma unroll
        for (int o = 4; o > 0; o >>= 1) r += __shfl_xor_sync(0xffffffffu, r, o);
        if (threadIdx.x == 0) red[0] = r;
    }
    __syncthreads();
    float r = red[0];
    __syncthreads();
    return r;
}

__global__ __launch_bounds__(256)
void add_ln_kernel(const float* __restrict__ x, const float* __restrict__ t,
                   const float* __restrict__ g, const float* __restrict__ bt,
                   float* __restrict__ dst, __half* __restrict__ dhi,
                   __half* __restrict__ dlo)
{
    __shared__ float red[8];
    size_t base = (size_t)blockIdx.x * Dm;
    float v[4]; float s = 0.f;
    #pragma unroll
    for (int e = 0; e < 4; e++) {
        int c = threadIdx.x + e * 256;
        v[e] = x[base + c] + t[base + c];
        s += v[e];
    }
    s = block_reduce_sum(s, red);
    float mu = s * (1.0f / Dm);
    float q = 0.f;
    #pragma unroll
    for (int e = 0; e < 4; e++) { float d = v[e] - mu; q += d * d; }
    q = block_reduce_sum(q, red);
    float inv = rsqrtf(q * (1.0f / Dm) + 1e-5f);
    #pragma unroll
    for (int e = 0; e < 4; e++) {
        int c = threadIdx.x + e * 256;
        float o = (v[e] - mu) * inv * g[c] + bt[c];
        dst[base + c] = o;
        if (dhi) {
            __half h = __float2half_rn(o);
            dhi[base + c] = h;
            dlo[base + c] = __float2half_rn(o - __half2float(h));
        }
    }
}

// ---------------------------------------------------------------------------
extern "C" void kernel_launch(void* const* d_in, const int* in_sizes, int n_in,
                              void* d_out, int out_size)
{
    const int*   src = (const int*)d_in[0];
    const int*   msk = (const int*)d_in[1];
    const float* emb = (const float*)d_in[2];
    const float* Wq  = (const float*)d_in[3];
    const float* bq  = (const float*)d_in[4];
    const float* Wk  = (const float*)d_in[5];
    const float* bk  = (const float*)d_in[6];
    const float* Wv  = (const float*)d_in[7];
    const float* bv  = (const float*)d_in[8];
    const float* Wo  = (const float*)d_in[9];
    const float* bo  = (const float*)d_in[10];
    const float* g1  = (const float*)d_in[11];
    const float* b1n = (const float*)d_in[12];
    const float* W1  = (const float*)d_in[13];
    const float* b1  = (const float*)d_in[14];
    const float* W2  = (const float*)d_in[15];
    const float* b2  = (const float*)d_in[16];
    const float* g2  = (const float*)d_in[17];
    const float* b2n = (const float*)d_in[18];
    float* out = (float*)d_out;

    float* f32 = nullptr;
    cudaGetSymbolAddress((void**)&f32, g_f32);
    float* X  = f32;
    float* T2 = f32 + (size_t)NTOK * Dm;

    __half *Xh, *Xl, *Qh, *Ql, *Ohb, *Olb, *Hh, *Hl, *Wt;
    float* bqkv;
    cudaGetSymbolAddress((void**)&Xh,  g_xh);
    cudaGetSymbolAddress((void**)&Xl,  g_xl);
    cudaGetSymbolAddress((void**)&Qh,  g_qkvh);
    cudaGetSymbolAddress((void**)&Ql,  g_qkvl);
    cudaGetSymbolAddress((void**)&Ohb, g_oh);
    cudaGetSymbolAddress((void**)&Olb, g_ol);
    cudaGetSymbolAddress((void**)&Hh,  g_hh);
    cudaGetSymbolAddress((void**)&Hl,  g_hl);
    cudaGetSymbolAddress((void**)&Wt,  g_wt);
    cudaGetSymbolAddress((void**)&bqkv, g_bqkv);

    cudaFuncSetAttribute((const void*)gemm_tc_kernel,
                         cudaFuncAttributeMaxDynamicSharedMemorySize, GEMM_SMEM);
    cudaFuncSetAttribute((const void*)attn_tc_kernel,
                         cudaFuncAttributeMaxDynamicSharedMemorySize, ATTN_SMEM);

    const size_t M1  = (size_t)1024 * 1024;
    const size_t LWT = 12 * M1;

    wt_convz_kernel<<<dim3(32, 32, NL), 256>>>(Wq, Wt,        Dm, Dm, (size_t)Dm*Dm, LWT);
    wt_convz_kernel<<<dim3(32, 32, NL), 256>>>(Wk, Wt + M1,   Dm, Dm, (size_t)Dm*Dm, LWT);
    wt_convz_kernel<<<dim3(32, 32, NL), 256>>>(Wv, Wt + 2*M1, Dm, Dm, (size_t)Dm*Dm, LWT);
    wt_convz_kernel<<<dim3(32, 32, NL), 256>>>(Wo, Wt + 3*M1, Dm, Dm, (size_t)Dm*Dm, LWT);
    wt_convz_kernel<<<dim3(Ff/32, Dm/32, NL), 256>>>(W1, Wt + 4*M1, Dm, Ff, (size_t)Dm*Ff, LWT);
    wt_convz_kernel<<<dim3(Dm/32, Ff/32, NL), 256>>>(W2, Wt + 8*M1, Ff, Dm, (size_t)Dm*Ff, LWT);
    pack_bias_kernel<<<NL * 3 * Dm / 256, 256>>>(bq, bk, bv, bqkv);

    embed_kernel<<<NTOK, 256>>>(src, emb, X, Xh, Xl);

    dim3 gQKV(3 * Dm / 128, NTOK / 128);  // (24, 64)
    dim3 gD(Dm / 128, NTOK / 128);        // (8, 64)
    dim3 gF(Ff / 128, NTOK / 128);        // (32, 64)
    dim3 gA(Sq / 128, Hn, Bz);            // (8, 16, 8)

    for (int l = 0; l < NL; l++) {
        size_t oD = (size_t)l * Dm, oF = (size_t)l * Ff;
        size_t wb = (size_t)l * LWT;
        bool last = (l == NL - 1);

        gemm_tc_kernel<<<gQKV, 256, GEMM_SMEM>>>(Xh, Xl, Wt + wb,
            bqkv + (size_t)l * 3 * Dm, nullptr, Qh, Ql, NTOK, 3 * Dm, Dm, 0);
        attn_tc_kernel<<<gA, 256, ATTN_SMEM>>>(Qh, Ql, msk, Ohb, Olb);
        gemm_tc_kernel<<<gD, 256, GEMM_SMEM>>>(Ohb, Olb, Wt + wb + 3*M1,
            bo + oD, T2, nullptr, nullptr, NTOK, Dm, Dm, 0);
        add_ln_kernel<<<NTOK, 256>>>(X, T2, g1 + oD, b1n + oD, X, Xh, Xl);
        gemm_tc_kernel<<<gF, 256, GEMM_SMEM>>>(Xh, Xl, Wt + wb + 4*M1,
            b1 + oF, nullptr, Hh, Hl, NTOK, Ff, Dm, 1);
        gemm_tc_kernel<<<gD, 256, GEMM_SMEM>>>(Hh, Hl, Wt + wb + 8*M1,
            b2 + oD, T2, nullptr, nullptr, NTOK, Dm, Ff, 0);
        add_ln_kernel<<<NTOK, 256>>>(X, T2, g2 + oD, b2n + oD,
            last ? out : X, last ? nullptr : Xh, Xl);
    }
}